// round 2
// baseline (speedup 1.0000x reference)
#include <cuda_runtime.h>

#define N_NODES 50000
#define N_EDGES 500000
#define NUMK 4
#define FDIM 64
#define DDIM 32
#define NBE 64
#define NBND 63
#define GP 68
#define FULL 0xffffffffu

// Scratch (device globals: no allocation allowed)
__device__ __align__(128) float g_y[(size_t)N_NODES * 128];  // per-node accumulated cat
__device__ float g_s[N_NODES];                               // per-node accumulated scale
__device__ float g_d0[N_NODES];
__device__ float g_d2[N_NODES];
__device__ __align__(128) float g_T[NBE * FDIM];             // bucket -> (embed @ G_w.T)
__device__ int g_cin[N_NODES];                               // in-degree (dst histogram)
__device__ int g_cout[N_NODES];                              // out-degree
__device__ int g_start[N_NODES];                             // CSR row starts (by dst)
__device__ int g_cur[N_NODES];                               // scatter cursors
__device__ int g_eidx[N_EDGES];                              // edge ids grouped by dst

__global__ void k_init() {
    int i = blockIdx.x * blockDim.x + threadIdx.x;
    if (i < N_NODES) { g_cin[i] = 0; g_cout[i] = 0; }
}

// T[b][f] = sum_d embed[b][d] * G_w[f][d]
__global__ void k_table(const float* __restrict__ emb, const float* __restrict__ gw) {
    int b = blockIdx.x, f = threadIdx.x;
    float acc = 0.f;
#pragma unroll
    for (int d = 0; d < DDIM; d++) acc += emb[b * DDIM + d] * gw[f * DDIM + d];
    g_T[b * FDIM + f] = acc;
}

__global__ void k_hist(const int* __restrict__ src, const int* __restrict__ dst) {
    int e = blockIdx.x * blockDim.x + threadIdx.x;
    if (e < N_EDGES) {
        atomicAdd(&g_cin[dst[e]], 1);
        atomicAdd(&g_cout[src[e]], 1);
    }
}

__global__ void k_norm() {
    int i = blockIdx.x * blockDim.x + threadIdx.x;
    if (i < N_NODES) {
        g_d0[i] = rsqrtf((float)max(g_cin[i], 1));
        g_d2[i] = rsqrtf((float)max(g_cout[i], 1));
    }
}

// Single-block exclusive prefix scan over g_cin -> g_start, g_cur
__global__ __launch_bounds__(1024) void k_scan() {
    __shared__ int wsum[32];
    __shared__ int s_carry;
    int tid = threadIdx.x, lane = tid & 31, wid = tid >> 5;
    if (tid == 0) s_carry = 0;
    __syncthreads();
    for (int base = 0; base < N_NODES; base += 1024) {
        int i = base + tid;
        int v = (i < N_NODES) ? g_cin[i] : 0;
        int x = v;
#pragma unroll
        for (int off = 1; off < 32; off <<= 1) {
            int y = __shfl_up_sync(FULL, x, off);
            if (lane >= off) x += y;
        }
        if (lane == 31) wsum[wid] = x;
        __syncthreads();
        if (wid == 0) {
            int y = wsum[lane];
#pragma unroll
            for (int off = 1; off < 32; off <<= 1) {
                int z = __shfl_up_sync(FULL, y, off);
                if (lane >= off) y += z;
            }
            wsum[lane] = y;
        }
        __syncthreads();
        int excl = x - v + (wid > 0 ? wsum[wid - 1] : 0) + s_carry;
        if (i < N_NODES) { g_start[i] = excl; g_cur[i] = excl; }
        __syncthreads();
        if (tid == 1023) s_carry = excl + v;
        __syncthreads();
    }
}

__global__ void k_scatter(const int* __restrict__ dst) {
    int e = blockIdx.x * blockDim.x + threadIdx.x;
    if (e < N_EDGES) {
        int p = atomicAdd(&g_cur[dst[e]], 1);
        g_eidx[p] = e;
    }
}

// One warp per dst node: accumulate cat row in registers, single write.
__global__ __launch_bounds__(256) void k_edge(
    const float* __restrict__ feat, const float* __restrict__ loc,
    const float* __restrict__ bnd,
    const int* __restrict__ src, const int* __restrict__ inter)
{
    __shared__ float sb[64];
    __shared__ int sbuf[8][160];   // per-warp (edge,slot) -> (other_id<<6)|bucket
    int t = threadIdx.x;
    if (t < NBND) sb[t] = bnd[t];
    __syncthreads();

    int lane = t & 31;
    int wl = t >> 5;
    int v = blockIdx.x * 8 + wl;
    if (v >= N_NODES) return;

    int start = g_start[v];
    int deg = g_cin[v];
    float vx = __ldg(&loc[v * 3]), vy = __ldg(&loc[v * 3 + 1]), vz = __ldg(&loc[v * 3 + 2]);

    float ax = 0.f, ay = 0.f, az = 0.f, aw = 0.f;   // accumulator (4 floats/lane)
    float ssum = 0.f;

    for (int base = 0; base < deg; base += 32) {
        int m = min(32, deg - base);
        int e = 0, si = 0; float w = 0.f;
        if (lane < m) {
            e = __ldg(&g_eidx[start + base + lane]);
            si = __ldg(&src[e]);
            w = __ldg(&g_d2[si]);
        }

        // ---- distance/bucket phase: m*5 work items across all lanes ----
        int items = m * 5;
#pragma unroll
        for (int tt = 0; tt < 5; tt++) {
            int it = tt * 32 + lane;
            bool act = it < items;
            int cl = act ? it : 0;
            int ke = cl / 5, slot = cl - ke * 5;
            int eid = __shfl_sync(FULL, e, ke);
            int sik = __shfl_sync(FULL, si, ke);
            if (act) {
                int other = (slot == 0) ? v : __ldg(&inter[eid * NUMK + slot - 1]);
                float bx = __ldg(&loc[other * 3]), by = __ldg(&loc[other * 3 + 1]), bz = __ldg(&loc[other * 3 + 2]);
                float sx = __ldg(&loc[sik * 3]),  sy = __ldg(&loc[sik * 3 + 1]),  sz = __ldg(&loc[sik * 3 + 2]);
                float dx = sx - bx, dy = sy - by, dz = sz - bz;
                float dv = sqrtf(dx * dx + dy * dy + dz * dz);
                int pos = 0;
#pragma unroll
                for (int step = 32; step >= 1; step >>= 1)
                    if (pos + step <= NBND && sb[pos + step - 1] < dv) pos += step;
                sbuf[wl][it] = (other << 6) | pos;
            }
        }
        __syncwarp();

        // ---- feature phase ----
        for (int k = 0; k < m; k++) {
            int sik = __shfl_sync(FULL, si, k);
            float wk = __shfl_sync(FULL, w, k);
            if (lane == 0) ssum += wk;
            if (lane < 16) {
                int j = lane * 4;
                int b1 = sbuf[wl][k * 5] & 63;
                float4 h  = *reinterpret_cast<const float4*>(feat + (size_t)sik * FDIM + j);
                float4 tv = *reinterpret_cast<const float4*>(g_T + b1 * FDIM + j);
                ax += wk * h.x * tv.x; ay += wk * h.y * tv.y;
                az += wk * h.z * tv.z; aw += wk * h.w * tv.w;
            } else {
                int j = (lane - 16) * 4;
                float tx = 0.f, ty = 0.f, tz = 0.f, tw = 0.f;
#pragma unroll
                for (int s = 1; s <= NUMK; s++) {
                    int pv = sbuf[wl][k * 5 + s];
                    int id = pv >> 6, bk = pv & 63;
                    float4 h  = *reinterpret_cast<const float4*>(feat + (size_t)id * FDIM + j);
                    float4 tv = *reinterpret_cast<const float4*>(g_T + bk * FDIM + j);
                    tx += h.x * tv.x; ty += h.y * tv.y;
                    tz += h.z * tv.z; tw += h.w * tv.w;
                }
                ax += wk * tx; ay += wk * ty; az += wk * tz; aw += wk * tw;
            }
        }
        __syncwarp();
    }

    float d0v = __ldg(&g_d0[v]);
    float scale = (lane < 16) ? d0v : d0v * 0.25f;
    int j = (lane < 16) ? lane * 4 : 64 + (lane - 16) * 4;
    float4 o = make_float4(ax * scale, ay * scale, az * scale, aw * scale);
    *reinterpret_cast<float4*>(g_y + (size_t)v * 128 + j) = o;
    if (lane == 0) g_s[v] = d0v * ssum;
}

// out[v][f] = sum_j y[v][j] * W[f][j] + s[v] * b[f]
__global__ __launch_bounds__(256) void k_gemm(
    const float* __restrict__ W, const float* __restrict__ bvec,
    float* __restrict__ out)
{
    extern __shared__ float smem[];
    float* sW = smem;             // [128][GP], j-major, indexed by f
    float* sY = smem + 128 * GP;  // [128][GP], j-major, indexed by v_local
    int t = threadIdx.x;
    int vbase = blockIdx.x * 64;

    for (int idx = t; idx < FDIM * 128; idx += 256) {
        int f = idx >> 7, j = idx & 127;
        sW[j * GP + f] = W[idx];
    }
    for (int idx = t; idx < 64 * 128; idx += 256) {
        int v = idx >> 7, j = idx & 127;
        int gv = vbase + v;
        sY[j * GP + v] = (gv < N_NODES) ? g_y[(size_t)gv * 128 + j] : 0.f;
    }
    __syncthreads();

    int f0 = (t & 15) * 4;
    int v0 = (t >> 4) * 4;
    float acc[4][4];
#pragma unroll
    for (int a = 0; a < 4; a++)
#pragma unroll
        for (int b = 0; b < 4; b++) acc[a][b] = 0.f;

#pragma unroll 4
    for (int j = 0; j < 128; j++) {
        float4 wv = *reinterpret_cast<float4*>(&sW[j * GP + f0]);
        float4 yv = *reinterpret_cast<float4*>(&sY[j * GP + v0]);
        float w[4] = {wv.x, wv.y, wv.z, wv.w};
        float y[4] = {yv.x, yv.y, yv.z, yv.w};
#pragma unroll
        for (int a = 0; a < 4; a++)
#pragma unroll
            for (int b = 0; b < 4; b++) acc[a][b] += y[a] * w[b];
    }

    float4 bb = *reinterpret_cast<const float4*>(bvec + f0);
#pragma unroll
    for (int a = 0; a < 4; a++) {
        int v = vbase + v0 + a;
        if (v < N_NODES) {
            float sv = g_s[v];
            float4 o;
            o.x = acc[a][0] + sv * bb.x;
            o.y = acc[a][1] + sv * bb.y;
            o.z = acc[a][2] + sv * bb.z;
            o.w = acc[a][3] + sv * bb.w;
            *reinterpret_cast<float4*>(out + (size_t)v * FDIM + f0) = o;
        }
    }
}

extern "C" void kernel_launch(void* const* d_in, const int* in_sizes, int n_in,
                              void* d_out, int out_size) {
    const float* feat = (const float*)d_in[0];
    const float* loc  = (const float*)d_in[1];
    const float* bnd  = (const float*)d_in[2];
    const float* emb  = (const float*)d_in[3];
    const float* gw   = (const float*)d_in[4];
    const float* aggw = (const float*)d_in[5];
    const float* aggb = (const float*)d_in[6];
    const int* src   = (const int*)d_in[7];
    const int* dst   = (const int*)d_in[8];
    const int* inter = (const int*)d_in[9];
    float* out = (float*)d_out;

    k_init<<<(N_NODES + 255) / 256, 256>>>();
    k_table<<<NBE, FDIM>>>(emb, gw);
    k_hist<<<(N_EDGES + 255) / 256, 256>>>(src, dst);
    k_norm<<<(N_NODES + 255) / 256, 256>>>();
    k_scan<<<1, 1024>>>();
    k_scatter<<<(N_EDGES + 255) / 256, 256>>>(dst);
    k_edge<<<(N_NODES + 7) / 8, 256>>>(feat, loc, bnd, src, inter);

    size_t smem = 2 * 128 * GP * sizeof(float);
    cudaFuncSetAttribute(k_gemm, cudaFuncAttributeMaxDynamicSharedMemorySize, (int)smem);
    k_gemm<<<(N_NODES + 63) / 64, 256, smem>>>(aggw, aggb, out);
}

// round 3
// speedup vs baseline: 1.2092x; 1.2092x over previous
#include <cuda_runtime.h>

#define N_NODES 50000
#define N_EDGES 500000
#define NUMK 4
#define FDIM 64
#define DDIM 32
#define NBE 64
#define NBND 63
#define GP 68
#define FULL 0xffffffffu
#define SCAN_B 1024
#define NSCAN ((N_NODES + SCAN_B - 1) / SCAN_B)   // 49

// Scratch (device globals: no allocation allowed)
__device__ __align__(128) float g_y[(size_t)N_NODES * 128];
__device__ float g_s[N_NODES];
__device__ float g_d0[N_NODES];
__device__ float g_d2[N_NODES];
__device__ __align__(128) float g_T[NBE * FDIM];
__device__ int g_cin[N_NODES];
__device__ int g_cout[N_NODES];
__device__ int g_start[N_NODES];
__device__ int g_cur[N_NODES];
__device__ int g_part[NSCAN];
__device__ int g_eidx[N_EDGES];

__device__ __forceinline__ void red_add4(float* p, float x, float y, float z, float w) {
    asm volatile("red.global.add.v4.f32 [%0], {%1,%2,%3,%4};"
                 :: "l"(p), "f"(x), "f"(y), "f"(z), "f"(w) : "memory");
}

__global__ void k_init() {
    int i = blockIdx.x * blockDim.x + threadIdx.x;
    int stride = gridDim.x * blockDim.x;
    float4 z = make_float4(0.f, 0.f, 0.f, 0.f);
    float4* y4 = reinterpret_cast<float4*>(g_y);
    for (int j = i; j < N_NODES * 32; j += stride) y4[j] = z;
    for (int j = i; j < N_NODES; j += stride) {
        g_cin[j] = 0; g_cout[j] = 0; g_s[j] = 0.f;
    }
}

__global__ void k_table(const float* __restrict__ emb, const float* __restrict__ gw) {
    int b = blockIdx.x, f = threadIdx.x;
    float acc = 0.f;
#pragma unroll
    for (int d = 0; d < DDIM; d++) acc += emb[b * DDIM + d] * gw[f * DDIM + d];
    g_T[b * FDIM + f] = acc;
}

__global__ void k_hist(const int* __restrict__ src, const int* __restrict__ dst) {
    int e = blockIdx.x * blockDim.x + threadIdx.x;
    if (e < N_EDGES) {
        atomicAdd(&g_cin[dst[e]], 1);
        atomicAdd(&g_cout[src[e]], 1);
    }
}

// Per-block local exclusive scan of g_cin -> g_start, block totals -> g_part.
// Also computes d0/d2 (fused norm).
__global__ __launch_bounds__(SCAN_B) void k_scanA() {
    __shared__ int wsum[32];
    int t = threadIdx.x, lane = t & 31, wid = t >> 5;
    int i = blockIdx.x * SCAN_B + t;
    int v = (i < N_NODES) ? g_cin[i] : 0;
    if (i < N_NODES) {
        g_d0[i] = rsqrtf((float)max(v, 1));
        g_d2[i] = rsqrtf((float)max(g_cout[i], 1));
    }
    int x = v;
#pragma unroll
    for (int off = 1; off < 32; off <<= 1) {
        int u = __shfl_up_sync(FULL, x, off);
        if (lane >= off) x += u;
    }
    if (lane == 31) wsum[wid] = x;
    __syncthreads();
    if (wid == 0) {
        int y = wsum[lane];
#pragma unroll
        for (int off = 1; off < 32; off <<= 1) {
            int z = __shfl_up_sync(FULL, y, off);
            if (lane >= off) y += z;
        }
        wsum[lane] = y;
    }
    __syncthreads();
    int excl = x - v + (wid > 0 ? wsum[wid - 1] : 0);
    if (i < N_NODES) g_start[i] = excl;
    if (t == SCAN_B - 1) g_part[blockIdx.x] = excl + v;
}

__global__ void k_scanB() {
    __shared__ int s[64];
    int t = threadIdx.x;
    int v = (t < NSCAN) ? g_part[t] : 0;
    s[t] = v;
    __syncthreads();
    int acc = v;
#pragma unroll
    for (int off = 1; off < 64; off <<= 1) {
        int u = (t >= off) ? s[t - off] : 0;
        __syncthreads();
        acc += u; s[t] = acc;
        __syncthreads();
    }
    if (t < NSCAN) g_part[t] = acc - v;   // exclusive
}

__global__ __launch_bounds__(SCAN_B) void k_scanC() {
    int i = blockIdx.x * SCAN_B + threadIdx.x;
    if (i < N_NODES) {
        int s0 = g_start[i] + g_part[blockIdx.x];
        g_start[i] = s0;
        g_cur[i] = s0;
    }
}

__global__ void k_scatter(const int* __restrict__ dst) {
    int e = blockIdx.x * blockDim.x + threadIdx.x;
    if (e < N_EDGES) {
        int p = atomicAdd(&g_cur[dst[e]], 1);
        g_eidx[p] = e;
    }
}

// One warp per 8 consecutive CSR-ordered edges; register accumulation with
// run-length merged red.v4 flushes.
__global__ __launch_bounds__(256) void k_edge(
    const float* __restrict__ feat, const float* __restrict__ loc,
    const float* __restrict__ bnd,
    const int* __restrict__ src, const int* __restrict__ dst,
    const int* __restrict__ inter)
{
    __shared__ float sb[64];
    __shared__ int sbuf[8][48];   // (other_id<<6)|bucket for 40 items per warp
    int t = threadIdx.x;
    if (t < NBND) sb[t] = bnd[t];
    __syncthreads();

    int lane = t & 31, w = t >> 5;
    long base = ((long)blockIdx.x * 8 + w) * 8;
    if (base >= N_EDGES) return;

    // lanes 0..7 hold this warp's 8 edge headers
    int e_l = 0, si_l = 0, di_l = 0;
    if (lane < 8) {
        e_l  = __ldg(&g_eidx[base + lane]);
        si_l = __ldg(&src[e_l]);
        di_l = __ldg(&dst[e_l]);
    }

    // ---- distance/bucket phase: 40 items over 2 passes ----
#pragma unroll
    for (int pass = 0; pass < 2; pass++) {
        int i = pass * 32 + lane;
        bool act = i < 40;
        int ic = act ? i : 0;
        int k = ic / 5, slot = ic - k * 5;
        int eid = __shfl_sync(FULL, e_l, k);
        int sik = __shfl_sync(FULL, si_l, k);
        int dik = __shfl_sync(FULL, di_l, k);
        if (act) {
            int other = (slot == 0) ? dik : __ldg(&inter[(size_t)eid * NUMK + slot - 1]);
            float sx = __ldg(&loc[sik * 3]),   sy = __ldg(&loc[sik * 3 + 1]),   sz = __ldg(&loc[sik * 3 + 2]);
            float bx = __ldg(&loc[other * 3]), by = __ldg(&loc[other * 3 + 1]), bz = __ldg(&loc[other * 3 + 2]);
            float dx = sx - bx, dy = sy - by, dz = sz - bz;
            float dv = sqrtf(dx * dx + dy * dy + dz * dz);
            int pos = 0;
#pragma unroll
            for (int step = 32; step >= 1; step >>= 1)
                if (pos + step <= NBND && sb[pos + step - 1] < dv) pos += step;
            sbuf[w][i] = (other << 6) | pos;
        }
    }
    __syncwarp();

    // ---- feature phase: 8 unrolled per-edge bodies, merged flushes ----
    float ax = 0.f, ay = 0.f, az = 0.f, aw = 0.f;
    float ssum = 0.f;
    int curdst = -1;
    int jpos = (lane < 16) ? lane * 4 : 64 + (lane - 16) * 4;
    int j2 = (lane < 16) ? lane * 4 : (lane - 16) * 4;

#pragma unroll
    for (int c = 0; c < 8; c++) {
        int sik = __shfl_sync(FULL, si_l, c);
        int dik = __shfl_sync(FULL, di_l, c);
        if (dik != curdst) {
            if (curdst >= 0) {
                red_add4(g_y + (size_t)curdst * 128 + jpos, ax, ay, az, aw);
                if (lane == 0) atomicAdd(&g_s[curdst], ssum);
            }
            ax = ay = az = aw = 0.f; ssum = 0.f;
            curdst = dik;
        }
        float sc = __ldg(&g_d0[dik]) * __ldg(&g_d2[sik]);
        if (lane == 0) ssum += sc;
        if (lane < 16) {
            int b1 = sbuf[w][c * 5] & 63;
            float4 h  = *reinterpret_cast<const float4*>(feat + (size_t)sik * FDIM + j2);
            float4 tv = *reinterpret_cast<const float4*>(g_T + b1 * FDIM + j2);
            ax += sc * h.x * tv.x; ay += sc * h.y * tv.y;
            az += sc * h.z * tv.z; aw += sc * h.w * tv.w;
        } else {
            float tx = 0.f, ty = 0.f, tz = 0.f, tw = 0.f;
#pragma unroll
            for (int s = 1; s <= NUMK; s++) {
                int pv = sbuf[w][c * 5 + s];
                int id = pv >> 6, bk = pv & 63;
                float4 h  = *reinterpret_cast<const float4*>(feat + (size_t)id * FDIM + j2);
                float4 tv = *reinterpret_cast<const float4*>(g_T + bk * FDIM + j2);
                tx += h.x * tv.x; ty += h.y * tv.y;
                tz += h.z * tv.z; tw += h.w * tv.w;
            }
            float f4 = sc * 0.25f;
            ax += f4 * tx; ay += f4 * ty; az += f4 * tz; aw += f4 * tw;
        }
    }
    if (curdst >= 0) {
        red_add4(g_y + (size_t)curdst * 128 + jpos, ax, ay, az, aw);
        if (lane == 0) atomicAdd(&g_s[curdst], ssum);
    }
}

// out[v][f] = sum_j y[v][j] * W[f][j] + s[v] * b[f]
__global__ __launch_bounds__(256) void k_gemm(
    const float* __restrict__ W, const float* __restrict__ bvec,
    float* __restrict__ out)
{
    extern __shared__ float smem[];
    float* sW = smem;
    float* sY = smem + 128 * GP;
    int t = threadIdx.x;
    int vbase = blockIdx.x * 64;

    for (int idx = t; idx < FDIM * 128; idx += 256) {
        int f = idx >> 7, j = idx & 127;
        sW[j * GP + f] = W[idx];
    }
    for (int idx = t; idx < 64 * 128; idx += 256) {
        int v = idx >> 7, j = idx & 127;
        int gv = vbase + v;
        sY[j * GP + v] = (gv < N_NODES) ? g_y[(size_t)gv * 128 + j] : 0.f;
    }
    __syncthreads();

    int f0 = (t & 15) * 4;
    int v0 = (t >> 4) * 4;
    float acc[4][4];
#pragma unroll
    for (int a = 0; a < 4; a++)
#pragma unroll
        for (int b = 0; b < 4; b++) acc[a][b] = 0.f;

#pragma unroll 4
    for (int j = 0; j < 128; j++) {
        float4 wv = *reinterpret_cast<float4*>(&sW[j * GP + f0]);
        float4 yv = *reinterpret_cast<float4*>(&sY[j * GP + v0]);
        float wr[4] = {wv.x, wv.y, wv.z, wv.w};
        float yr[4] = {yv.x, yv.y, yv.z, yv.w};
#pragma unroll
        for (int a = 0; a < 4; a++)
#pragma unroll
            for (int b = 0; b < 4; b++) acc[a][b] += yr[a] * wr[b];
    }

    float4 bb = *reinterpret_cast<const float4*>(bvec + f0);
#pragma unroll
    for (int a = 0; a < 4; a++) {
        int v = vbase + v0 + a;
        if (v < N_NODES) {
            float sv = g_s[v];
            float4 o;
            o.x = acc[a][0] + sv * bb.x;
            o.y = acc[a][1] + sv * bb.y;
            o.z = acc[a][2] + sv * bb.z;
            o.w = acc[a][3] + sv * bb.w;
            *reinterpret_cast<float4*>(out + (size_t)v * FDIM + f0) = o;
        }
    }
}

extern "C" void kernel_launch(void* const* d_in, const int* in_sizes, int n_in,
                              void* d_out, int out_size) {
    const float* feat = (const float*)d_in[0];
    const float* loc  = (const float*)d_in[1];
    const float* bnd  = (const float*)d_in[2];
    const float* emb  = (const float*)d_in[3];
    const float* gw   = (const float*)d_in[4];
    const float* aggw = (const float*)d_in[5];
    const float* aggb = (const float*)d_in[6];
    const int* src   = (const int*)d_in[7];
    const int* dst   = (const int*)d_in[8];
    const int* inter = (const int*)d_in[9];
    float* out = (float*)d_out;

    k_init<<<1024, 256>>>();
    k_table<<<NBE, FDIM>>>(emb, gw);
    k_hist<<<(N_EDGES + 255) / 256, 256>>>(src, dst);
    k_scanA<<<NSCAN, SCAN_B>>>();
    k_scanB<<<1, 64>>>();
    k_scanC<<<NSCAN, SCAN_B>>>();
    k_scatter<<<(N_EDGES + 255) / 256, 256>>>(dst);
    // 62500 warps, 8 per block
    k_edge<<<(N_EDGES / 8 + 7) / 8, 256>>>(feat, loc, bnd, src, dst, inter);

    size_t smem = 2 * 128 * GP * sizeof(float);
    cudaFuncSetAttribute(k_gemm, cudaFuncAttributeMaxDynamicSharedMemorySize, (int)smem);
    k_gemm<<<(N_NODES + 63) / 64, 256, smem>>>(aggw, aggb, out);
}

// round 4
// speedup vs baseline: 1.2487x; 1.0326x over previous
#include <cuda_runtime.h>
#include <cuda_fp16.h>

#define N_NODES 50000
#define N_EDGES 500000
#define NUMK 4
#define FDIM 64
#define DDIM 32
#define NBE 64
#define NBND 63
#define GP 68
#define FULL 0xffffffffu

// Scratch (device globals: no allocation allowed)
__device__ __align__(128) float g_y[(size_t)N_NODES * 128];   // accumulated cat rows
__device__ float g_s[N_NODES];
__device__ float g_d0[N_NODES];
__device__ float g_d2[N_NODES];
__device__ __align__(128) float g_T[NBE * FDIM];              // bucket -> embed@G^T
__device__ __align__(128) __half g_fh[(size_t)N_NODES * FDIM]; // fp16 feature copy

__device__ __forceinline__ void red_add4(float* p, float x, float y, float z, float w) {
    asm volatile("red.global.add.v4.f32 [%0], {%1,%2,%3,%4};"
                 :: "l"(p), "f"(x), "f"(y), "f"(z), "f"(w) : "memory");
}

// Fused prep: zero g_y, zero degree accumulators + g_s, build T table,
// convert feat -> fp16.
__global__ __launch_bounds__(256) void k_prep(
    const float* __restrict__ emb, const float* __restrict__ gw,
    const float* __restrict__ feat)
{
    int i = blockIdx.x * blockDim.x + threadIdx.x;
    int stride = gridDim.x * blockDim.x;

    float4 z = make_float4(0.f, 0.f, 0.f, 0.f);
    float4* y4 = reinterpret_cast<float4*>(g_y);
    for (int j = i; j < N_NODES * 32; j += stride) y4[j] = z;

    // feat fp32 -> fp16 (process as float2 -> half2)
    const float2* f2 = reinterpret_cast<const float2*>(feat);
    __half2* h2 = reinterpret_cast<__half2*>(g_fh);
    for (int j = i; j < N_NODES * FDIM / 2; j += stride) {
        float2 v = f2[j];
        h2[j] = __floats2half2_rn(v.x, v.y);
    }

    for (int j = i; j < N_NODES; j += stride) {
        g_d0[j] = 0.f; g_d2[j] = 0.f; g_s[j] = 0.f;
    }

    // T[b][f] = sum_d emb[b][d] * gw[f][d]   (4096 entries)
    for (int j = i; j < NBE * FDIM; j += stride) {
        int b = j >> 6, f = j & 63;
        float acc = 0.f;
#pragma unroll
        for (int d = 0; d < DDIM; d++) acc += emb[b * DDIM + d] * gw[f * DDIM + d];
        g_T[j] = acc;
    }
}

__global__ void k_deg(const int* __restrict__ src, const int* __restrict__ dst) {
    int e = blockIdx.x * blockDim.x + threadIdx.x;
    if (e < N_EDGES) {
        atomicAdd(&g_d0[dst[e]], 1.f);
        atomicAdd(&g_d2[src[e]], 1.f);
    }
}

__global__ void k_norm() {
    int i = blockIdx.x * blockDim.x + threadIdx.x;
    if (i < N_NODES) {
        g_d0[i] = rsqrtf(fmaxf(g_d0[i], 1.f));
        g_d2[i] = rsqrtf(fmaxf(g_d2[i], 1.f));
    }
}

// One warp per edge. fp16 feature gathers, fp32 accumulate, red.v4 scatter.
__global__ __launch_bounds__(256) void k_edge(
    const float* __restrict__ loc, const float* __restrict__ bnd,
    const int* __restrict__ src, const int* __restrict__ dst,
    const int* __restrict__ inter)
{
    __shared__ float sb2[64];   // squared boundaries
    int t = threadIdx.x;
    if (t < NBND) { float b = bnd[t]; sb2[t] = b * b; }
    __syncthreads();

    int lane = t & 31;
    int e = blockIdx.x * 8 + (t >> 5);
    if (e >= N_EDGES) return;

    int si = __ldg(&src[e]);
    int di = __ldg(&dst[e]);

    int other = 0, pos = 0;
    if (lane < 5) {
        other = (lane == 0) ? di : __ldg(&inter[(size_t)e * NUMK + lane - 1]);
        float ax = __ldg(&loc[si * 3]),    ay = __ldg(&loc[si * 3 + 1]),    az = __ldg(&loc[si * 3 + 2]);
        float bx = __ldg(&loc[other * 3]), by = __ldg(&loc[other * 3 + 1]), bz = __ldg(&loc[other * 3 + 2]);
        float dx = ax - bx, dy = ay - by, dz = az - bz;
        float d2 = dx * dx + dy * dy + dz * dz;   // compare squared vs squared bounds
#pragma unroll
        for (int step = 32; step >= 1; step >>= 1)
            if (pos + step <= NBND && sb2[pos + step - 1] < d2) pos += step;
    }
    unsigned m = FULL;
    int b1  = __shfl_sync(m, pos, 0);
    int bk0 = __shfl_sync(m, pos, 1), bk1 = __shfl_sync(m, pos, 2);
    int bk2 = __shfl_sync(m, pos, 3), bk3 = __shfl_sync(m, pos, 4);
    int i0  = __shfl_sync(m, other, 1), i1 = __shfl_sync(m, other, 2);
    int i2  = __shfl_sync(m, other, 3), i3 = __shfl_sync(m, other, 4);

    float sc = __ldg(&g_d0[di]) * __ldg(&g_d2[si]);
    float* yrow = g_y + (size_t)di * 128;

    if (lane < 16) {
        int j = lane * 4;
        const __half2* hp = reinterpret_cast<const __half2*>(g_fh + (size_t)si * FDIM + j);
        float2 h0 = __half22float2(hp[0]);
        float2 h1 = __half22float2(hp[1]);
        float4 tt = *reinterpret_cast<const float4*>(g_T + b1 * FDIM + j);
        red_add4(yrow + j, sc * h0.x * tt.x, sc * h0.y * tt.y,
                           sc * h1.x * tt.z, sc * h1.y * tt.w);
        if (lane == 0) atomicAdd(&g_s[di], sc);
    } else {
        int j = (lane - 16) * 4;
        float ax = 0.f, ay = 0.f, az = 0.f, aw = 0.f;
        int ids[4] = {i0, i1, i2, i3};
        int bks[4] = {bk0, bk1, bk2, bk3};
#pragma unroll
        for (int k = 0; k < NUMK; k++) {
            const __half2* hp = reinterpret_cast<const __half2*>(g_fh + (size_t)ids[k] * FDIM + j);
            float2 h0 = __half22float2(hp[0]);
            float2 h1 = __half22float2(hp[1]);
            float4 tt = *reinterpret_cast<const float4*>(g_T + bks[k] * FDIM + j);
            ax += h0.x * tt.x; ay += h0.y * tt.y;
            az += h1.x * tt.z; aw += h1.y * tt.w;
        }
        float f4 = sc * 0.25f;
        red_add4(yrow + 64 + j, f4 * ax, f4 * ay, f4 * az, f4 * aw);
    }
}

// out[v][f] = sum_j y[v][j] * W[f][j] + s[v] * b[f]
__global__ __launch_bounds__(256) void k_gemm(
    const float* __restrict__ W, const float* __restrict__ bvec,
    float* __restrict__ out)
{
    extern __shared__ float smem[];
    float* sW = smem;             // [128][GP] j-major, by f
    float* sY = smem + 128 * GP;  // [128][GP] j-major, by v_local
    int t = threadIdx.x;
    int vbase = blockIdx.x * 64;

    for (int idx = t; idx < FDIM * 128; idx += 256) {
        int f = idx >> 7, j = idx & 127;
        sW[j * GP + f] = W[idx];
    }
    for (int idx = t; idx < 64 * 128; idx += 256) {
        int v = idx >> 7, j = idx & 127;
        int gv = vbase + v;
        sY[j * GP + v] = (gv < N_NODES) ? g_y[(size_t)gv * 128 + j] : 0.f;
    }
    __syncthreads();

    int f0 = (t & 15) * 4;
    int v0 = (t >> 4) * 4;
    float acc[4][4];
#pragma unroll
    for (int a = 0; a < 4; a++)
#pragma unroll
        for (int b = 0; b < 4; b++) acc[a][b] = 0.f;

#pragma unroll 4
    for (int j = 0; j < 128; j++) {
        float4 wv = *reinterpret_cast<float4*>(&sW[j * GP + f0]);
        float4 yv = *reinterpret_cast<float4*>(&sY[j * GP + v0]);
        float wr[4] = {wv.x, wv.y, wv.z, wv.w};
        float yr[4] = {yv.x, yv.y, yv.z, yv.w};
#pragma unroll
        for (int a = 0; a < 4; a++)
#pragma unroll
            for (int b = 0; b < 4; b++) acc[a][b] += yr[a] * wr[b];
    }

    float4 bb = *reinterpret_cast<const float4*>(bvec + f0);
#pragma unroll
    for (int a = 0; a < 4; a++) {
        int v = vbase + v0 + a;
        if (v < N_NODES) {
            float sv = g_s[v];
            float4 o;
            o.x = acc[a][0] + sv * bb.x;
            o.y = acc[a][1] + sv * bb.y;
            o.z = acc[a][2] + sv * bb.z;
            o.w = acc[a][3] + sv * bb.w;
            *reinterpret_cast<float4*>(out + (size_t)v * FDIM + f0) = o;
        }
    }
}

extern "C" void kernel_launch(void* const* d_in, const int* in_sizes, int n_in,
                              void* d_out, int out_size) {
    const float* feat = (const float*)d_in[0];
    const float* loc  = (const float*)d_in[1];
    const float* bnd  = (const float*)d_in[2];
    const float* emb  = (const float*)d_in[3];
    const float* gw   = (const float*)d_in[4];
    const float* aggw = (const float*)d_in[5];
    const float* aggb = (const float*)d_in[6];
    const int* src   = (const int*)d_in[7];
    const int* dst   = (const int*)d_in[8];
    const int* inter = (const int*)d_in[9];
    float* out = (float*)d_out;

    k_prep<<<1024, 256>>>(emb, gw, feat);                      // launch 1
    k_deg<<<(N_EDGES + 255) / 256, 256>>>(src, dst);           // launch 2
    k_norm<<<(N_NODES + 255) / 256, 256>>>();                  // launch 3
    k_edge<<<(N_EDGES + 7) / 8, 256>>>(loc, bnd, src, dst, inter); // launch 4 (profiled)
    size_t smem = 2 * 128 * GP * sizeof(float);
    cudaFuncSetAttribute(k_gemm, cudaFuncAttributeMaxDynamicSharedMemorySize, (int)smem);
    k_gemm<<<(N_NODES + 63) / 64, 256, smem>>>(aggw, aggb, out);   // launch 5
}